// round 16
// baseline (speedup 1.0000x reference)
#include <cuda_runtime.h>
#include <math.h>

#define M_ANCH   589824
#define NCLS     80
#define K_TOP    1000
#define CAND_CAP 8192
#define HSHIFT   18                     /* 14-bit logit histogram */
#define NHBINS   16384
#define GRID_P1  576
#define GRID_R   148
#define NTHR     256
#define NWARPS   (GRID_R * (NTHR / 32)) /* 1184 */
#define NKEY4    (M_ANCH / 4)           /* 147456 */
#define RSTRIDE  (GRID_R * NTHR)        /* 37888 */
#define IMG_INV  (1.0f/2048.0f)
#define SCALE_CLAMP 4.1351665567423560f /* log(1000/16) */

// ---------------- scratch (device globals; no allocations allowed) ----------
__device__ unsigned            g_key[M_ANCH];       // logit-ordered bits
__device__ unsigned            g_hist[NHBINS];      // starts 0; re-zeroed in K3
__device__ unsigned            g_candCount;
__device__ unsigned long long  g_cand[CAND_CAP];    // (sigmoid-key<<32)|~idx
__device__ float4              g_boxes[K_TOP];
__device__ int                 g_labels[K_TOP];
__device__ unsigned            g_validw[32];

// ---------------- helpers ---------------------------------------------------
__device__ __forceinline__ unsigned f2ord(float f) {
    unsigned u = __float_as_uint(f);
    return (u & 0x80000000u) ? ~u : (u | 0x80000000u);
}
__device__ __forceinline__ float ord2f(unsigned o) {
    return (o & 0x80000000u) ? __uint_as_float(o & 0x7FFFFFFFu)
                             : __uint_as_float(~o);
}
// Sigmoid matching XLA lowering of lax.logistic on GPU (bit-stable vs ref).
__device__ __forceinline__ float ref_sigmoid(float x) {
    float e = expf(-x);
    return __fdiv_rn(1.0f, __fadd_rn(1.0f, e));
}

// ---------------- K1: rowmax (pipelined) + logit key + 14-bit hist ----------
__global__ void __launch_bounds__(NTHR, 4)
k_p1(const float* __restrict__ cls) {
    __shared__ unsigned shp[NHBINS / 2];     // packed u16 pair counters, 32KB
    const int t = threadIdx.x;
    const int b = blockIdx.x;
    const int warpId = t >> 5;
    const int lane = t & 31;
    const int g = lane >> 2;
    const int gl = lane & 3;

    for (int e = t; e < NHBINS / 2; e += NTHR) shp[e] = 0u;
    __syncthreads();

    const int rowBase = b * 1024 + warpId * 128 + g;
    const float* basep = cls + (size_t)rowBase * NCLS + gl * 4;

    float4 A0, A1, A2, A3, A4;
    {
        const float* rp = basep;
        A0 = *(const float4*)(rp);
        A1 = *(const float4*)(rp + 16);
        A2 = *(const float4*)(rp + 32);
        A3 = *(const float4*)(rp + 48);
        A4 = *(const float4*)(rp + 64);
    }
#pragma unroll 2
    for (int p = 0; p < 16; p++) {
        int pn = (p < 15) ? p + 1 : 15;
        const float* rp = basep + (size_t)pn * 8 * NCLS;
        float4 B0 = *(const float4*)(rp);
        float4 B1 = *(const float4*)(rp + 16);
        float4 B2 = *(const float4*)(rp + 32);
        float4 B3 = *(const float4*)(rp + 48);
        float4 B4 = *(const float4*)(rp + 64);

        float m = fmaxf(fmaxf(A0.x, A0.y), fmaxf(A0.z, A0.w));
        m = fmaxf(m, fmaxf(fmaxf(A1.x, A1.y), fmaxf(A1.z, A1.w)));
        m = fmaxf(m, fmaxf(fmaxf(A2.x, A2.y), fmaxf(A2.z, A2.w)));
        m = fmaxf(m, fmaxf(fmaxf(A3.x, A3.y), fmaxf(A3.z, A3.w)));
        m = fmaxf(m, fmaxf(fmaxf(A4.x, A4.y), fmaxf(A4.z, A4.w)));
        m = fmaxf(m, __shfl_xor_sync(0xffffffffu, m, 1));
        m = fmaxf(m, __shfl_xor_sync(0xffffffffu, m, 2));
        if (gl == 0) {
            unsigned key = f2ord(m);
            g_key[rowBase + p * 8] = key;
            unsigned bin = key >> HSHIFT;
            atomicAdd(&shp[bin >> 1], 1u << ((bin & 1u) << 4));
        }
        A0 = B0; A1 = B1; A2 = B2; A3 = B3; A4 = B4;
    }
    __syncthreads();
    for (int e = t; e < NHBINS / 2; e += NTHR) {
        unsigned v = shp[e];
        unsigned lo = v & 0xFFFFu, hi = v >> 16;
        if (lo) atomicAdd(&g_hist[2 * e], lo);
        if (hi) atomicAdd(&g_hist[2 * e + 1], hi);
    }
}

// ---------------- K2: find threshold (register-resident) + compact ----------
__global__ void __launch_bounds__(NTHR)
k_sel() {
    __shared__ unsigned ssum[NTHR];
    __shared__ unsigned sbest;
    const int t = threadIdx.x;
    const int b = blockIdx.x;
    const int lane = t & 31;

    // load this thread's 64 bins as independent LDGs, keep in registers
    unsigned h[64];
#pragma unroll
    for (int e = 0; e < 64; e++) h[e] = g_hist[t * 64 + e];
    unsigned s = 0;
#pragma unroll
    for (int e = 0; e < 64; e++) s += h[e];
    ssum[t] = s;
    if (t == 0) sbest = 0u;
    __syncthreads();
    for (int off = 1; off < NTHR; off <<= 1) {
        unsigned a = (t + off < NTHR) ? ssum[t + off] : 0u;
        __syncthreads();
        ssum[t] += a;
        __syncthreads();
    }
    unsigned run = ssum[t] - s;          // strictly-higher threads' total
    unsigned best = 0;
#pragma unroll
    for (int e = 63; e >= 0; e--) {      // branch-free reverse scan in regs
        run += h[e];
        if (run >= K_TOP && best == 0u) best = (unsigned)(t * 64 + e);
    }
    if (best) atomicMax(&sbest, best);
    __syncthreads();
    unsigned B = sbest;
    unsigned thr = (B > 0 ? B - 1 : 0) << HSHIFT;   // one-bin tie margin

    const uint4* kp = (const uint4*)g_key;
#pragma unroll
    for (int it = 0; it < 4; it++) {
        int idx = b * NTHR + t + it * RSTRIDE;
        bool inb = idx < NKEY4;
        uint4 k4 = inb ? kp[idx] : make_uint4(0u, 0u, 0u, 0u);
        int i0 = idx * 4;
        unsigned keys[4] = { k4.x, k4.y, k4.z, k4.w };
#pragma unroll
        for (int c = 0; c < 4; c++) {
            bool f = inb && (keys[c] >= thr);
            unsigned bal = __ballot_sync(0xffffffffu, f);
            if (bal) {
                unsigned base;
                if (lane == 0)
                    base = atomicAdd(&g_candCount, (unsigned)__popc(bal));
                base = __shfl_sync(0xffffffffu, base, 0);
                if (f) {
                    unsigned pos = base + __popc(bal & ((1u << lane) - 1u));
                    if (pos < CAND_CAP) {
                        unsigned skey = f2ord(ref_sigmoid(ord2f(keys[c])));
                        g_cand[pos] = ((unsigned long long)skey << 32) |
                                      (unsigned)(~(i0 + c));
                    }
                }
            }
        }
    }
    if (b == 100 && t < 32) g_validw[t] = 0u;
}

// ---------------- K3: warp-per-candidate rank + cooperative decode ----------
__global__ void __launch_bounds__(NTHR, 2)
k_rank(const float* __restrict__ cls, const float* __restrict__ reg,
       const float* __restrict__ anc, float* __restrict__ out) {
    extern __shared__ unsigned long long sc[];
    const int t = threadIdx.x;
    const int b = blockIdx.x;
    const int warpId = t >> 5;
    const int lane = t & 31;
    unsigned cnt = min(g_candCount, (unsigned)CAND_CAP);

    for (unsigned j = t; j < cnt; j += NTHR) sc[j] = g_cand[j];
    __syncthreads();

    int gw = b * (NTHR / 32) + warpId;
    for (unsigned c = (unsigned)gw; c < cnt; c += NWARPS) {
        unsigned long long my = sc[c];
        unsigned r = 0;
        for (unsigned j = lane; j < cnt; j += 32) r += (sc[j] > my);
        r = __reduce_add_sync(0xffffffffu, r);
        if (r < K_TOP) {
            int i = (int)(~(unsigned)(my & 0xFFFFFFFFULL));
            int j = (int)r;
            const float4* row = (const float4*)(cls + (size_t)i * NCLS);
            unsigned long long bkey = 0ULL;
            if (lane < NCLS / 4) {
                float4 v = row[lane];
                float s0 = ref_sigmoid(v.x), s1 = ref_sigmoid(v.y);
                float s2 = ref_sigmoid(v.z), s3 = ref_sigmoid(v.w);
                unsigned long long k0 = ((unsigned long long)f2ord(s0) << 32) |
                                        (unsigned)(~(4 * lane + 0));
                unsigned long long k1 = ((unsigned long long)f2ord(s1) << 32) |
                                        (unsigned)(~(4 * lane + 1));
                unsigned long long k2 = ((unsigned long long)f2ord(s2) << 32) |
                                        (unsigned)(~(4 * lane + 2));
                unsigned long long k3 = ((unsigned long long)f2ord(s3) << 32) |
                                        (unsigned)(~(4 * lane + 3));
                bkey = max(max(k0, k1), max(k2, k3));
            }
#pragma unroll
            for (int off = 16; off >= 1; off >>= 1) {
                unsigned long long o = __shfl_xor_sync(0xffffffffu, bkey, off);
                if (o > bkey) bkey = o;
            }
            if (lane == 0) {
                float best = ord2f((unsigned)(bkey >> 32));
                int bl = (int)(~(unsigned)(bkey & 0xFFFFFFFFULL));
                float4 rg = ((const float4*)reg)[i];
                float4 an = ((const float4*)anc)[i];
                float ox = fminf(fmaxf(rg.x * an.z, -32.0f), 32.0f);
                float oy = fminf(fmaxf(rg.y * an.w, -32.0f), 32.0f);
                float cx = an.x + ox, cy = an.y + oy;
                float w = an.z * expf(fminf(rg.z, SCALE_CLAMP));
                float h = an.w * expf(fminf(rg.w, SCALE_CLAMP));
                float x1 = fminf(fmaxf((cx - 0.5f * w) * IMG_INV, 0.0f), 1.0f);
                float y1 = fminf(fmaxf((cy - 0.5f * h) * IMG_INV, 0.0f), 1.0f);
                float x2 = fminf(fmaxf((cx + 0.5f * w) * IMG_INV, 0.0f), 1.0f);
                float y2 = fminf(fmaxf((cy + 0.5f * h) * IMG_INV, 0.0f), 1.0f);
                out[4 * j + 0] = x1; out[4 * j + 1] = y1;
                out[4 * j + 2] = x2; out[4 * j + 3] = y2;
                out[4000 + j] = best;
                out[5000 + j] = (float)bl;
                g_boxes[j] = make_float4(x1, y1, x2, y2);
                g_labels[j] = bl;
                if (best >= 0.05f)
                    atomicOr(&g_validw[j >> 5], 1u << (j & 31));
            }
        }
    }
    // cleanup for next run: hist
    {
        int z = b * NTHR + t;
        if (z < NHBINS) g_hist[z] = 0u;
    }
}

// ---------------- K4: per-class parallel greedy NMS (one block) -------------
__global__ void __launch_bounds__(1024, 1)
k_nms(float* __restrict__ out) {
    __shared__ float4         s_box[K_TOP];      // 16 KB
    __shared__ int            s_lab[K_TOP];      //  4 KB
    __shared__ unsigned short s_ord[K_TOP];      //  2 KB
    __shared__ unsigned char  s_keep[K_TOP];     //  1 KB
    __shared__ int            s_cnt[NCLS];
    __shared__ int            s_off[NCLS + 1];
    __shared__ unsigned       s_valid[32];
    const int t = threadIdx.x;

    if (t < K_TOP) { s_box[t] = g_boxes[t]; s_lab[t] = g_labels[t]; }
    if (t < NCLS) s_cnt[t] = 0;
    if (t < 32) s_valid[t] = g_validw[t];
    if (t == 0) g_candCount = 0u;                 // reset for next run
    __syncthreads();

    // counting sort by class (slot order nondeterministic; sorted below)
    int myslot = -1;
    if (t < K_TOP) myslot = atomicAdd(&s_cnt[s_lab[t]], 1);
    __syncthreads();
    if (t == 0) {
        int acc = 0;
        for (int c = 0; c < NCLS; c++) { s_off[c] = acc; acc += s_cnt[c]; }
        s_off[NCLS] = acc;
    }
    __syncthreads();
    if (t < K_TOP) s_ord[s_off[s_lab[t]] + myslot] = (unsigned short)t;
    __syncthreads();

    // thread c: insertion-sort class c's candidates ascending by index,
    // then run the per-class greedy chain (exact reference order).
    if (t < NCLS) {
        int base = s_off[t], n = s_cnt[t];
        for (int a = 1; a < n; a++) {
            unsigned short v = s_ord[base + a];
            int p = a - 1;
            while (p >= 0 && s_ord[base + p] > v) {
                s_ord[base + p + 1] = s_ord[base + p];
                p--;
            }
            s_ord[base + p + 1] = v;
        }
        for (int a = 0; a < n; a++) {
            int i = (int)s_ord[base + a];
            bool valid = (s_valid[i >> 5] >> (i & 31)) & 1u;
            bool ov = false;
            if (valid) {
                float4 bi = s_box[i];
                float ai = (bi.z - bi.x) * (bi.w - bi.y);
                for (int bq = 0; bq < a; bq++) {
                    int j = (int)s_ord[base + bq];
                    if (!s_keep[j]) continue;
                    float4 bj = s_box[j];
                    float xx1 = fmaxf(bi.x, bj.x), yy1 = fmaxf(bi.y, bj.y);
                    float xx2 = fminf(bi.z, bj.z), yy2 = fminf(bi.w, bj.w);
                    float ww = fmaxf(1e-10f, xx2 - xx1);
                    float hh = fmaxf(1e-10f, yy2 - yy1);
                    float inter = ww * hh;
                    float aj = (bj.z - bj.x) * (bj.w - bj.y);
                    float iou = inter / (ai + aj - inter + 1e-10f);
                    if (iou > 0.6f) { ov = true; break; }
                }
            }
            s_keep[i] = (valid && !ov) ? 1 : 0;
        }
    }
    __syncthreads();

    if (t < K_TOP) out[6000 + t] = s_keep[t] ? 1.0f : 0.0f;
}

// ---------------- launcher ---------------------------------------------------
extern "C" void kernel_launch(void* const* d_in, const int* in_sizes, int n_in,
                              void* d_out, int out_size) {
    const float* cls = (const float*)d_in[0];
    const float* reg = (const float*)d_in[1];
    const float* anc = (const float*)d_in[2];
    float* out = (float*)d_out;
    (void)in_sizes; (void)n_in; (void)out_size;

    cudaFuncSetAttribute(k_rank, cudaFuncAttributeMaxDynamicSharedMemorySize,
                         CAND_CAP * (int)sizeof(unsigned long long));

    k_p1<<<GRID_P1, NTHR>>>(cls);
    k_sel<<<GRID_R, NTHR>>>();
    k_rank<<<GRID_R, NTHR, CAND_CAP * sizeof(unsigned long long)>>>(cls, reg, anc, out);
    k_nms<<<1, 1024>>>(out);
}

// round 17
// speedup vs baseline: 1.1092x; 1.1092x over previous
#include <cuda_runtime.h>
#include <math.h>

#define M_ANCH   589824
#define NCLS     80
#define K_TOP    1000
#define CAND_CAP 8192
#define HSHIFT   18                     /* 14-bit logit histogram */
#define NHBINS   16384
#define GRID_P1  576
#define GRID_R   148
#define NTHR     256
#define NWARPS   (GRID_R * (NTHR / 32)) /* 1184 */
#define NKEY4    (M_ANCH / 4)           /* 147456 */
#define RSTRIDE  (GRID_R * NTHR)        /* 37888 */
#define IMG_INV  (1.0f/2048.0f)
#define SCALE_CLAMP 4.1351665567423560f /* log(1000/16) */

// ---------------- scratch (device globals; no allocations allowed) ----------
__device__ unsigned            g_key[M_ANCH];       // logit-ordered bits
__device__ unsigned            g_hist[NHBINS];      // starts 0; re-zeroed in K3
__device__ unsigned            g_candCount;
__device__ unsigned long long  g_cand[CAND_CAP];    // (sigmoid-key<<32)|~idx
__device__ float4              g_boxes[K_TOP];
__device__ int                 g_labels[K_TOP];
__device__ unsigned            g_validw[32];

// ---------------- helpers ---------------------------------------------------
__device__ __forceinline__ unsigned f2ord(float f) {
    unsigned u = __float_as_uint(f);
    return (u & 0x80000000u) ? ~u : (u | 0x80000000u);
}
__device__ __forceinline__ float ord2f(unsigned o) {
    return (o & 0x80000000u) ? __uint_as_float(o & 0x7FFFFFFFu)
                             : __uint_as_float(~o);
}
// Sigmoid matching XLA lowering of lax.logistic on GPU (bit-stable vs ref).
__device__ __forceinline__ float ref_sigmoid(float x) {
    float e = expf(-x);
    return __fdiv_rn(1.0f, __fadd_rn(1.0f, e));
}

// ---------------- K1: rowmax (pipelined) + logit key + 14-bit hist ----------
__global__ void __launch_bounds__(NTHR, 4)
k_p1(const float* __restrict__ cls) {
    __shared__ unsigned shp[NHBINS / 2];     // packed u16 pair counters, 32KB
    const int t = threadIdx.x;
    const int b = blockIdx.x;
    const int warpId = t >> 5;
    const int lane = t & 31;
    const int g = lane >> 2;
    const int gl = lane & 3;

    for (int e = t; e < NHBINS / 2; e += NTHR) shp[e] = 0u;
    __syncthreads();

    const int rowBase = b * 1024 + warpId * 128 + g;
    const float* basep = cls + (size_t)rowBase * NCLS + gl * 4;

    float4 A0, A1, A2, A3, A4;
    {
        const float* rp = basep;
        A0 = *(const float4*)(rp);
        A1 = *(const float4*)(rp + 16);
        A2 = *(const float4*)(rp + 32);
        A3 = *(const float4*)(rp + 48);
        A4 = *(const float4*)(rp + 64);
    }
#pragma unroll 2
    for (int p = 0; p < 16; p++) {
        int pn = (p < 15) ? p + 1 : 15;
        const float* rp = basep + (size_t)pn * 8 * NCLS;
        float4 B0 = *(const float4*)(rp);
        float4 B1 = *(const float4*)(rp + 16);
        float4 B2 = *(const float4*)(rp + 32);
        float4 B3 = *(const float4*)(rp + 48);
        float4 B4 = *(const float4*)(rp + 64);

        float m = fmaxf(fmaxf(A0.x, A0.y), fmaxf(A0.z, A0.w));
        m = fmaxf(m, fmaxf(fmaxf(A1.x, A1.y), fmaxf(A1.z, A1.w)));
        m = fmaxf(m, fmaxf(fmaxf(A2.x, A2.y), fmaxf(A2.z, A2.w)));
        m = fmaxf(m, fmaxf(fmaxf(A3.x, A3.y), fmaxf(A3.z, A3.w)));
        m = fmaxf(m, fmaxf(fmaxf(A4.x, A4.y), fmaxf(A4.z, A4.w)));
        m = fmaxf(m, __shfl_xor_sync(0xffffffffu, m, 1));
        m = fmaxf(m, __shfl_xor_sync(0xffffffffu, m, 2));
        if (gl == 0) {
            unsigned key = f2ord(m);
            g_key[rowBase + p * 8] = key;
            unsigned bin = key >> HSHIFT;
            atomicAdd(&shp[bin >> 1], 1u << ((bin & 1u) << 4));
        }
        A0 = B0; A1 = B1; A2 = B2; A3 = B3; A4 = B4;
    }
    __syncthreads();
    for (int e = t; e < NHBINS / 2; e += NTHR) {
        unsigned v = shp[e];
        unsigned lo = v & 0xFFFFu, hi = v >> 16;
        if (lo) atomicAdd(&g_hist[2 * e], lo);
        if (hi) atomicAdd(&g_hist[2 * e + 1], hi);
    }
}

// ---------------- K2: find threshold (register-resident) + compact ----------
__global__ void __launch_bounds__(NTHR)
k_sel() {
    __shared__ unsigned ssum[NTHR];
    __shared__ unsigned sbest;
    const int t = threadIdx.x;
    const int b = blockIdx.x;
    const int lane = t & 31;

    // load this thread's 64 bins as independent LDGs, keep in registers
    unsigned h[64];
#pragma unroll
    for (int e = 0; e < 64; e++) h[e] = g_hist[t * 64 + e];
    unsigned s = 0;
#pragma unroll
    for (int e = 0; e < 64; e++) s += h[e];
    ssum[t] = s;
    if (t == 0) sbest = 0u;
    __syncthreads();
    for (int off = 1; off < NTHR; off <<= 1) {
        unsigned a = (t + off < NTHR) ? ssum[t + off] : 0u;
        __syncthreads();
        ssum[t] += a;
        __syncthreads();
    }
    unsigned run = ssum[t] - s;          // strictly-higher threads' total
    unsigned best = 0;
#pragma unroll
    for (int e = 63; e >= 0; e--) {      // branch-free reverse scan in regs
        run += h[e];
        if (run >= K_TOP && best == 0u) best = (unsigned)(t * 64 + e);
    }
    if (best) atomicMax(&sbest, best);
    __syncthreads();
    unsigned B = sbest;
    unsigned thr = (B > 0 ? B - 1 : 0) << HSHIFT;   // one-bin tie margin

    const uint4* kp = (const uint4*)g_key;
#pragma unroll
    for (int it = 0; it < 4; it++) {
        int idx = b * NTHR + t + it * RSTRIDE;
        bool inb = idx < NKEY4;
        uint4 k4 = inb ? kp[idx] : make_uint4(0u, 0u, 0u, 0u);
        int i0 = idx * 4;
        unsigned keys[4] = { k4.x, k4.y, k4.z, k4.w };
#pragma unroll
        for (int c = 0; c < 4; c++) {
            bool f = inb && (keys[c] >= thr);
            unsigned bal = __ballot_sync(0xffffffffu, f);
            if (bal) {
                unsigned base;
                if (lane == 0)
                    base = atomicAdd(&g_candCount, (unsigned)__popc(bal));
                base = __shfl_sync(0xffffffffu, base, 0);
                if (f) {
                    unsigned pos = base + __popc(bal & ((1u << lane) - 1u));
                    if (pos < CAND_CAP) {
                        unsigned skey = f2ord(ref_sigmoid(ord2f(keys[c])));
                        g_cand[pos] = ((unsigned long long)skey << 32) |
                                      (unsigned)(~(i0 + c));
                    }
                }
            }
        }
    }
    if (b == 100 && t < 32) g_validw[t] = 0u;
}

// ---------------- K3: warp-per-candidate rank + cooperative decode ----------
__global__ void __launch_bounds__(NTHR, 2)
k_rank(const float* __restrict__ cls, const float* __restrict__ reg,
       const float* __restrict__ anc, float* __restrict__ out) {
    extern __shared__ unsigned long long sc[];
    const int t = threadIdx.x;
    const int b = blockIdx.x;
    const int warpId = t >> 5;
    const int lane = t & 31;
    unsigned cnt = min(g_candCount, (unsigned)CAND_CAP);

    for (unsigned j = t; j < cnt; j += NTHR) sc[j] = g_cand[j];
    __syncthreads();

    int gw = b * (NTHR / 32) + warpId;
    for (unsigned c = (unsigned)gw; c < cnt; c += NWARPS) {
        unsigned long long my = sc[c];
        unsigned r = 0;
        for (unsigned j = lane; j < cnt; j += 32) r += (sc[j] > my);
        r = __reduce_add_sync(0xffffffffu, r);
        if (r < K_TOP) {
            int i = (int)(~(unsigned)(my & 0xFFFFFFFFULL));
            int j = (int)r;
            const float4* row = (const float4*)(cls + (size_t)i * NCLS);
            unsigned long long bkey = 0ULL;
            if (lane < NCLS / 4) {
                float4 v = row[lane];
                float s0 = ref_sigmoid(v.x), s1 = ref_sigmoid(v.y);
                float s2 = ref_sigmoid(v.z), s3 = ref_sigmoid(v.w);
                unsigned long long k0 = ((unsigned long long)f2ord(s0) << 32) |
                                        (unsigned)(~(4 * lane + 0));
                unsigned long long k1 = ((unsigned long long)f2ord(s1) << 32) |
                                        (unsigned)(~(4 * lane + 1));
                unsigned long long k2 = ((unsigned long long)f2ord(s2) << 32) |
                                        (unsigned)(~(4 * lane + 2));
                unsigned long long k3 = ((unsigned long long)f2ord(s3) << 32) |
                                        (unsigned)(~(4 * lane + 3));
                bkey = max(max(k0, k1), max(k2, k3));
            }
#pragma unroll
            for (int off = 16; off >= 1; off >>= 1) {
                unsigned long long o = __shfl_xor_sync(0xffffffffu, bkey, off);
                if (o > bkey) bkey = o;
            }
            if (lane == 0) {
                float best = ord2f((unsigned)(bkey >> 32));
                int bl = (int)(~(unsigned)(bkey & 0xFFFFFFFFULL));
                float4 rg = ((const float4*)reg)[i];
                float4 an = ((const float4*)anc)[i];
                float ox = fminf(fmaxf(rg.x * an.z, -32.0f), 32.0f);
                float oy = fminf(fmaxf(rg.y * an.w, -32.0f), 32.0f);
                float cx = an.x + ox, cy = an.y + oy;
                float w = an.z * expf(fminf(rg.z, SCALE_CLAMP));
                float h = an.w * expf(fminf(rg.w, SCALE_CLAMP));
                float x1 = fminf(fmaxf((cx - 0.5f * w) * IMG_INV, 0.0f), 1.0f);
                float y1 = fminf(fmaxf((cy - 0.5f * h) * IMG_INV, 0.0f), 1.0f);
                float x2 = fminf(fmaxf((cx + 0.5f * w) * IMG_INV, 0.0f), 1.0f);
                float y2 = fminf(fmaxf((cy + 0.5f * h) * IMG_INV, 0.0f), 1.0f);
                out[4 * j + 0] = x1; out[4 * j + 1] = y1;
                out[4 * j + 2] = x2; out[4 * j + 3] = y2;
                out[4000 + j] = best;
                out[5000 + j] = (float)bl;
                g_boxes[j] = make_float4(x1, y1, x2, y2);
                g_labels[j] = bl;
                if (best >= 0.05f)
                    atomicOr(&g_validw[j >> 5], 1u << (j & 31));
            }
        }
    }
    // cleanup for next run: hist
    {
        int z = b * NTHR + t;
        if (z < NHBINS) g_hist[z] = 0u;
    }
}

// ---------------- K4: warp-per-class greedy NMS (one block) -----------------
__global__ void __launch_bounds__(1024, 1)
k_nms(float* __restrict__ out) {
    __shared__ float4         s_box[K_TOP];      // 16 KB
    __shared__ int            s_lab[K_TOP];      //  4 KB
    __shared__ unsigned short s_ord[K_TOP];      //  2 KB
    __shared__ unsigned char  s_keep[K_TOP];     //  1 KB
    __shared__ int            s_cnt[NCLS];
    __shared__ int            s_off[NCLS + 1];
    __shared__ unsigned       s_valid[32];
    const int t = threadIdx.x;
    const int lane = t & 31;
    const int w = t >> 5;

    if (t < K_TOP) { s_box[t] = g_boxes[t]; s_lab[t] = g_labels[t]; }
    if (t < NCLS) s_cnt[t] = 0;
    if (t < 32) s_valid[t] = g_validw[t];
    if (t == 0) g_candCount = 0u;                 // reset for next run
    __syncthreads();

    // counting sort by class (slot order nondeterministic; sorted below)
    int myslot = -1;
    if (t < K_TOP) myslot = atomicAdd(&s_cnt[s_lab[t]], 1);
    __syncthreads();
    if (t == 0) {
        int acc = 0;
        for (int c = 0; c < NCLS; c++) { s_off[c] = acc; acc += s_cnt[c]; }
        s_off[NCLS] = acc;
    }
    __syncthreads();
    if (t < K_TOP) s_ord[s_off[s_lab[t]] + myslot] = (unsigned short)t;
    __syncthreads();

    // warp w handles classes w, w+32, w+64 — lanes cooperate per class
    for (int c = w; c < NCLS; c += 32) {
        int base = s_off[c], n = s_cnt[c];
        // lane 0: insertion-sort ascending by global index (exact ref order)
        if (lane == 0) {
            for (int a = 1; a < n; a++) {
                unsigned short v = s_ord[base + a];
                int p = a - 1;
                while (p >= 0 && s_ord[base + p] > v) {
                    s_ord[base + p + 1] = s_ord[base + p];
                    p--;
                }
                s_ord[base + p + 1] = v;
            }
        }
        __syncwarp();
        // greedy chain: lanes test predecessors in parallel, one vote/step
        for (int a = 0; a < n; a++) {
            int i = (int)s_ord[base + a];
            float4 bi = s_box[i];
            float ai = (bi.z - bi.x) * (bi.w - bi.y);
            bool myov = false;
            for (int bq = lane; bq < a; bq += 32) {
                int j = (int)s_ord[base + bq];
                if (s_keep[j]) {
                    float4 bj = s_box[j];
                    float xx1 = fmaxf(bi.x, bj.x), yy1 = fmaxf(bi.y, bj.y);
                    float xx2 = fminf(bi.z, bj.z), yy2 = fminf(bi.w, bj.w);
                    float ww = fmaxf(1e-10f, xx2 - xx1);
                    float hh = fmaxf(1e-10f, yy2 - yy1);
                    float inter = ww * hh;
                    float aj = (bj.z - bj.x) * (bj.w - bj.y);
                    float iou = inter / (ai + aj - inter + 1e-10f);
                    if (iou > 0.6f) myov = true;
                }
            }
            bool ov = __any_sync(0xffffffffu, myov);
            if (lane == 0) {
                bool valid = (s_valid[i >> 5] >> (i & 31)) & 1u;
                s_keep[i] = (valid && !ov) ? 1 : 0;
            }
            __syncwarp();
        }
    }
    __syncthreads();

    if (t < K_TOP) out[6000 + t] = s_keep[t] ? 1.0f : 0.0f;
}

// ---------------- launcher ---------------------------------------------------
extern "C" void kernel_launch(void* const* d_in, const int* in_sizes, int n_in,
                              void* d_out, int out_size) {
    const float* cls = (const float*)d_in[0];
    const float* reg = (const float*)d_in[1];
    const float* anc = (const float*)d_in[2];
    float* out = (float*)d_out;
    (void)in_sizes; (void)n_in; (void)out_size;

    cudaFuncSetAttribute(k_rank, cudaFuncAttributeMaxDynamicSharedMemorySize,
                         CAND_CAP * (int)sizeof(unsigned long long));

    k_p1<<<GRID_P1, NTHR>>>(cls);
    k_sel<<<GRID_R, NTHR>>>();
    k_rank<<<GRID_R, NTHR, CAND_CAP * sizeof(unsigned long long)>>>(cls, reg, anc, out);
    k_nms<<<1, 1024>>>(out);
}